// round 9
// baseline (speedup 1.0000x reference)
#include <cuda_runtime.h>
#include <cuda_bf16.h>

// Problem shape (fixed by the reference setup_inputs)
#define BB 1024
#define MM 256
#define LL 256

// Single-wave schedule: grid (64, 16) = 1024 CTAs <= 148 SMs * 8 resident.
// Each CTA: 256 threads x 4 m-rows x 64 batches. Per thread: one (m,l4) slot,
// 64 coalesced float4 stores. Batch loop split into 2 chunks of 32 so a full
// warp's lanes carry the x/sincos(x) values (one strided load per chunk),
// broadcast per iteration via dynamic-lane shuffle.
#define B_PER_CTA 64
#define B_CHUNK   32

__device__ __forceinline__ float elem(float xv, float sx2, float cx2,
                                      float iv, float niv,
                                      float phv, float cpv, float spv) {
    float diff = xv - phv;                    // identical fp32 op to reference
    bool mask = (diff > niv) & (diff <= iv);  // exact reference semantics
    // val = 0.5*cos(x-phi)+0.5 = cp*(0.5*cx) + sp*(0.5*sx) + 0.5
    float val = fmaf(cpv, cx2, fmaf(spv, sx2, 0.5f));
    return mask ? val : 0.0f;
}

__global__ void __launch_bounds__(256)
bcos_fused_kernel(const float* __restrict__ x,
                  const float* __restrict__ phis,
                  const float* __restrict__ interval,
                  float4* __restrict__ out) {
    int tid   = threadIdx.x;
    int ml4   = blockIdx.x * 256 + tid;    // 0..16383
    int m     = ml4 >> 6;                  // warp-uniform (64 slots per m)
    int lane  = tid & 31;
    int bbase = blockIdx.y * B_PER_CTA;

    float iv  = __ldg(interval + m);
    float niv = -iv;

    // Per-thread phi sincos (amortized over 64 stores)
    float4 ph = reinterpret_cast<const float4*>(phis)[ml4];
    float spx, cpx, spy, cpy, spz, cpz, spw, cpw;
    sincosf(ph.x, &spx, &cpx);
    sincosf(ph.y, &spy, &cpy);
    sincosf(ph.z, &spz, &cpz);
    sincosf(ph.w, &spw, &cpw);

    float4* op = out + (size_t)bbase * (MM * LL / 4) + ml4;

    for (int c = 0; c < B_PER_CTA / B_CHUNK; c++) {
        // Lane l holds x / 0.5*sincos(x) for batch b0+l
        int b0 = bbase + c * B_CHUNK;
        float my_x = __ldg(x + (b0 + lane) * MM + m);
        float s0, c0;
        sincosf(my_x, &s0, &c0);
        float my_s = 0.5f * s0;
        float my_c = 0.5f * c0;

#pragma unroll 4
        for (int i = 0; i < B_CHUNK; i++) {
            float xv = __shfl_sync(0xffffffffu, my_x, i);
            float s2 = __shfl_sync(0xffffffffu, my_s, i);
            float c2 = __shfl_sync(0xffffffffu, my_c, i);

            float4 o;
            o.x = elem(xv, s2, c2, iv, niv, ph.x, cpx, spx);
            o.y = elem(xv, s2, c2, iv, niv, ph.y, cpy, spy);
            o.z = elem(xv, s2, c2, iv, niv, ph.z, cpz, spz);
            o.w = elem(xv, s2, c2, iv, niv, ph.w, cpw, spw);

            __stcs(op, o);                 // streaming store: don't pollute L2
            op += MM * LL / 4;
        }
    }
}

extern "C" void kernel_launch(void* const* d_in, const int* in_sizes, int n_in,
                              void* d_out, int out_size) {
    const float* x        = (const float*)d_in[0];  // (1024, 256)
    const float* phis     = (const float*)d_in[1];  // (256, 256)
    const float* interval = (const float*)d_in[2];  // (256,)
    float4* out = (float4*)d_out;                   // (1024, 65536) fp32

    dim3 grid(MM * LL / 4 / 256, BB / B_PER_CTA);   // (64, 16) = 1024 CTAs
    bcos_fused_kernel<<<grid, 256>>>(x, phis, interval, out);
}